// round 1
// baseline (speedup 1.0000x reference)
#include <cuda_runtime.h>
#include <cuda_bf16.h>
#include <math.h>

// Problem constants
#define Bk 128     // batch
#define Sk 200     // seq len
#define Dk 512     // model dim
#define Hk 8       // heads
#define DFk 64     // per-head dim
#define ROWS (Bk * Sk)          // 25600
#define SCALE 0.125f            // 1/sqrt(64)

// ---------------- device scratch (no allocations allowed) ----------------
__device__ float g_Qp[(size_t)Bk * Hk * Sk * DFk];   // [B,H,S,DF]
__device__ float g_Kp[(size_t)Bk * Hk * Sk * DFk];
__device__ float g_Vp[(size_t)Bk * Hk * Sk * DFk];
__device__ float g_ctx[(size_t)ROWS * Dk];           // [B,S,H*DF]

// ---------------- tiled SGEMM core: C[M,N] = X[M,K] * W^T + bias ---------
// BM=128, BN=128, BK=16, 256 threads, 8x8 per thread.
#define BM 128
#define BN 128
#define BKK 16

struct Acc { float v[8][8]; };

__device__ __forceinline__ void sgemm_body(const float* __restrict__ X,
                                           const float* __restrict__ W,
                                           int m0, int n0, Acc& acc)
{
    __shared__ float As[BKK * BM];
    __shared__ float Bs[BKK * BN];

    const int tid  = threadIdx.x;
    const int lrow = tid >> 2;          // 0..63
    const int lcol = (tid & 3) * 4;     // 0,4,8,12
    const int tr   = tid >> 4;          // 0..15
    const int tc   = tid & 15;          // 0..15

#pragma unroll
    for (int i = 0; i < 8; i++)
#pragma unroll
        for (int j = 0; j < 8; j++) acc.v[i][j] = 0.f;

    for (int k0 = 0; k0 < Dk; k0 += BKK) {
        // load X tile (transpose into As[k][m])
        {
            const float* xg = X + (size_t)(m0 + lrow) * Dk + k0 + lcol;
            float4 xa = *(const float4*)xg;
            float4 xb = *(const float4*)(xg + (size_t)64 * Dk);
            As[(lcol + 0) * BM + lrow]      = xa.x;
            As[(lcol + 1) * BM + lrow]      = xa.y;
            As[(lcol + 2) * BM + lrow]      = xa.z;
            As[(lcol + 3) * BM + lrow]      = xa.w;
            As[(lcol + 0) * BM + lrow + 64] = xb.x;
            As[(lcol + 1) * BM + lrow + 64] = xb.y;
            As[(lcol + 2) * BM + lrow + 64] = xb.z;
            As[(lcol + 3) * BM + lrow + 64] = xb.w;
        }
        // load W tile (W row-major [n][k]; transpose into Bs[k][n])
        {
            const float* wg = W + (size_t)(n0 + lrow) * Dk + k0 + lcol;
            float4 wa = *(const float4*)wg;
            float4 wb = *(const float4*)(wg + (size_t)64 * Dk);
            Bs[(lcol + 0) * BN + lrow]      = wa.x;
            Bs[(lcol + 1) * BN + lrow]      = wa.y;
            Bs[(lcol + 2) * BN + lrow]      = wa.z;
            Bs[(lcol + 3) * BN + lrow]      = wa.w;
            Bs[(lcol + 0) * BN + lrow + 64] = wb.x;
            Bs[(lcol + 1) * BN + lrow + 64] = wb.y;
            Bs[(lcol + 2) * BN + lrow + 64] = wb.z;
            Bs[(lcol + 3) * BN + lrow + 64] = wb.w;
        }
        __syncthreads();

        const float* Asp = As + tr * 8;
        const float* Bsp = Bs + tc * 8;
#pragma unroll
        for (int k = 0; k < BKK; k++) {
            float4 a0 = *(const float4*)(Asp + k * BM);
            float4 a1 = *(const float4*)(Asp + k * BM + 4);
            float4 b0 = *(const float4*)(Bsp + k * BN);
            float4 b1 = *(const float4*)(Bsp + k * BN + 4);
            float a[8] = {a0.x, a0.y, a0.z, a0.w, a1.x, a1.y, a1.z, a1.w};
            float b[8] = {b0.x, b0.y, b0.z, b0.w, b1.x, b1.y, b1.z, b1.w};
#pragma unroll
            for (int i = 0; i < 8; i++)
#pragma unroll
                for (int j = 0; j < 8; j++)
                    acc.v[i][j] = fmaf(a[i], b[j], acc.v[i][j]);
        }
        __syncthreads();
    }
}

// QKV projection GEMM. blockIdx.z selects {q,k,v}; writes [B,H,S,DF] layout.
__global__ __launch_bounds__(256, 2)
void qkv_gemm_kernel(const float* __restrict__ q, const float* __restrict__ k,
                     const float* __restrict__ v,
                     const float* __restrict__ Wq, const float* __restrict__ bq,
                     const float* __restrict__ Wk, const float* __restrict__ bk,
                     const float* __restrict__ Wv, const float* __restrict__ bv)
{
    const int z  = blockIdx.z;
    const float* X    = (z == 0) ? q  : (z == 1) ? k  : v;
    const float* W    = (z == 0) ? Wq : (z == 1) ? Wk : Wv;
    const float* bias = (z == 0) ? bq : (z == 1) ? bk : bv;
    float* out        = (z == 0) ? g_Qp : (z == 1) ? g_Kp : g_Vp;

    const int m0 = blockIdx.y * BM;
    const int n0 = blockIdx.x * BN;

    Acc acc;
    sgemm_body(X, W, m0, n0, acc);

    const int tr = threadIdx.x >> 4;
    const int tc = threadIdx.x & 15;
#pragma unroll
    for (int i = 0; i < 8; i++) {
        const int m = m0 + tr * 8 + i;
        const int bb = m / Sk;
        const int ss = m - bb * Sk;
#pragma unroll
        for (int j = 0; j < 8; j++) {
            const int n  = n0 + tc * 8 + j;
            const int hh = n >> 6;
            const int df = n & 63;
            float val = acc.v[i][j] + bias[n];
            out[(((size_t)bb * Hk + hh) * Sk + ss) * DFk + df] = val;
        }
    }
}

// Output projection: d_out[m][n] = ctx @ Wo^T + bo
__global__ __launch_bounds__(256, 2)
void out_gemm_kernel(const float* __restrict__ Wo, const float* __restrict__ bo,
                     float* __restrict__ out)
{
    const int m0 = blockIdx.y * BM;
    const int n0 = blockIdx.x * BN;

    Acc acc;
    sgemm_body(g_ctx, Wo, m0, n0, acc);

    const int tr = threadIdx.x >> 4;
    const int tc = threadIdx.x & 15;
#pragma unroll
    for (int i = 0; i < 8; i++) {
        const int m = m0 + tr * 8 + i;
#pragma unroll
        for (int j = 0; j < 8; j++) {
            const int n = n0 + tc * 8 + j;
            out[(size_t)m * Dk + n] = acc.v[i][j] + bo[n];
        }
    }
}

// ---------------- attention: one block per (b,h) ----------------
// smem: Ks[200*65], Vs[200*65], Ps[8*200], Qs[8*64]
#define KV_LD 65
#define ATTN_SMEM_FLOATS (2 * Sk * KV_LD + 8 * Sk + 8 * DFk)

__global__ __launch_bounds__(256, 2)
void attn_kernel(float* __restrict__ ctx)
{
    extern __shared__ float sm[];
    float* Ks = sm;
    float* Vs = Ks + Sk * KV_LD;
    float* Ps = Vs + Sk * KV_LD;
    float* Qs = Ps + 8 * Sk;

    const int bh = blockIdx.x;            // b*H + h
    const int bb = bh >> 3;
    const int hh = bh & 7;
    const size_t base = (size_t)bh * Sk * DFk;
    const float* Qg = g_Qp + base;
    const float* Kg = g_Kp + base;
    const float* Vg = g_Vp + base;

    const int tid = threadIdx.x;
    // stage K, V into padded smem
    for (int i = tid; i < Sk * DFk; i += 256) {
        const int r = i >> 6;
        const int c = i & 63;
        Ks[r * KV_LD + c] = Kg[i];
        Vs[r * KV_LD + c] = Vg[i];
    }
    __syncthreads();

    const int w    = tid >> 5;
    const int lane = tid & 31;
    float* Pw = Ps + w * Sk;

    for (int qi = w; qi < Sk; qi += 8) {
        // query row -> smem -> regs
        Qs[w * DFk + lane]      = Qg[qi * DFk + lane];
        Qs[w * DFk + 32 + lane] = Qg[qi * DFk + 32 + lane];
        __syncwarp();
        float qreg[DFk];
#pragma unroll
        for (int d = 0; d < DFk; d++) qreg[d] = Qs[w * DFk + d];

        const int nk = qi + 1;     // causal: keys 0..qi
        float sc[7];
        float mx = -INFINITY;
        int cnt = 0;
        for (int kk = lane; kk < nk; kk += 32) {
            const float* kr = Ks + kk * KV_LD;
            float s = 0.f;
#pragma unroll
            for (int d = 0; d < DFk; d++) s = fmaf(qreg[d], kr[d], s);
            s *= SCALE;
            sc[cnt++] = s;
            mx = fmaxf(mx, s);
        }
#pragma unroll
        for (int off = 16; off > 0; off >>= 1)
            mx = fmaxf(mx, __shfl_xor_sync(0xFFFFFFFFu, mx, off));

        float lsum = 0.f;
        cnt = 0;
        for (int kk = lane; kk < nk; kk += 32) {
            float e = expf(sc[cnt++] - mx);
            Pw[kk] = e;
            lsum += e;
        }
#pragma unroll
        for (int off = 16; off > 0; off >>= 1)
            lsum += __shfl_xor_sync(0xFFFFFFFFu, lsum, off);
        const float inv = 1.f / lsum;
        __syncwarp();

        // AV: lane handles df = lane and lane+32
        float a0 = 0.f, a1 = 0.f;
        for (int kk = 0; kk < nk; kk++) {
            const float p = Pw[kk];
            a0 = fmaf(p, Vs[kk * KV_LD + lane],      a0);
            a1 = fmaf(p, Vs[kk * KV_LD + 32 + lane], a1);
        }
        a0 *= inv; a1 *= inv;
        if (qi == 0) { a0 = 0.f; a1 = 0.f; }   // zero_pad: attn row 0 zeroed
        float* o = g_ctx + ((size_t)bb * Sk + qi) * Dk + hh * DFk;
        o[lane]      = a0;
        o[lane + 32] = a1;
        __syncwarp();
    }
    (void)ctx;
}

// ---------------- launch ----------------
extern "C" void kernel_launch(void* const* d_in, const int* in_sizes, int n_in,
                              void* d_out, int out_size)
{
    const float* q  = (const float*)d_in[0];
    const float* k  = (const float*)d_in[1];
    const float* v  = (const float*)d_in[2];
    const float* Wq = (const float*)d_in[3];
    const float* bq = (const float*)d_in[4];
    const float* Wk = (const float*)d_in[5];
    const float* bk = (const float*)d_in[6];
    const float* Wv = (const float*)d_in[7];
    const float* bv = (const float*)d_in[8];
    const float* Wo = (const float*)d_in[9];
    const float* bo = (const float*)d_in[10];
    float* out = (float*)d_out;

    // QKV projections
    dim3 g1(Dk / BN, ROWS / BM, 3);
    qkv_gemm_kernel<<<g1, 256>>>(q, k, v, Wq, bq, Wk, bk, Wv, bv);

    // attention
    const int smem_bytes = ATTN_SMEM_FLOATS * (int)sizeof(float);
    cudaFuncSetAttribute(attn_kernel, cudaFuncAttributeMaxDynamicSharedMemorySize,
                         smem_bytes);
    attn_kernel<<<Bk * Hk, 256, smem_bytes>>>(nullptr);

    // output projection
    dim3 g3(Dk / BN, ROWS / BM, 1);
    out_gemm_kernel<<<g3, 256>>>(Wo, bo, out);
}

// round 3
// speedup vs baseline: 1.5938x; 1.5938x over previous
#include <cuda_runtime.h>
#include <cuda_bf16.h>
#include <math.h>
#include <stdint.h>

// Problem constants
#define Bk 128
#define Sk 200
#define Dk 512
#define Hk 8
#define DFk 64
#define ROWS (Bk * Sk)          // 25600
#define SCALE 0.125f

typedef __nv_bfloat16 bf16;

// ---------------- device scratch ----------------
__device__ __align__(256) float g_Qp[(size_t)ROWS * Dk];
__device__ __align__(256) float g_Kp[(size_t)ROWS * Dk];
__device__ __align__(256) float g_Vp[(size_t)ROWS * Dk];
__device__ __align__(256) bf16  g_xhi[3][(size_t)ROWS * Dk];   // q,k,v split-hi
__device__ __align__(256) bf16  g_xlo[3][(size_t)ROWS * Dk];   // q,k,v split-lo
__device__ __align__(256) bf16  g_whi[4][(size_t)Dk * Dk];     // Wq,Wk,Wv,Wo hi
__device__ __align__(256) bf16  g_wlo[4][(size_t)Dk * Dk];     // lo
__device__ __align__(256) bf16  g_chi[(size_t)ROWS * Dk];      // ctx hi
__device__ __align__(256) bf16  g_clo[(size_t)ROWS * Dk];      // ctx lo

// ---------------- mma.sync + cp.async helpers (base sm_103 target) ----------
#define MMA16816(d, a, b)                                                      \
    asm volatile(                                                              \
        "mma.sync.aligned.m16n8k16.row.col.f32.bf16.bf16.f32 "                 \
        "{%0,%1,%2,%3}, {%4,%5,%6,%7}, {%8,%9}, {%0,%1,%2,%3};"                \
        : "+f"((d)[0]), "+f"((d)[1]), "+f"((d)[2]), "+f"((d)[3])               \
        : "r"((a)[0]), "r"((a)[1]), "r"((a)[2]), "r"((a)[3]),                  \
          "r"((b)[0]), "r"((b)[1]))

static __device__ __forceinline__ void cp_async16(uint32_t saddr, const void* gaddr) {
    asm volatile("cp.async.cg.shared.global [%0], [%1], 16;"
                 :: "r"(saddr), "l"(gaddr));
}
static __device__ __forceinline__ void cp_commit() {
    asm volatile("cp.async.commit_group;" ::: "memory");
}
template <int N>
static __device__ __forceinline__ void cp_wait() {
    asm volatile("cp.async.wait_group %0;" :: "n"(N) : "memory");
}

// ---------------- GEMM config ----------------
// C[M,N] = X[M,512] * W[N,512]^T, 3-split bf16.
// CTA 128x128, BK=32, 8 warps (2 m x 4 n), warp tile 64x32.
#define BKC 32
#define NCH (Dk / BKC)          // 16 chunks
#define ROWE 40                 // padded row length in bf16 (80 B)
#define TILE_B (128 * ROWE * 2) // 10240 bytes per sub-tile
#define STG_B  (4 * TILE_B)     // Ah, Al, Bh, Bl = 40960 bytes per stage
#define GEMM_SMEM (2 * STG_B)   // 81920

// Load one K-chunk (32 cols) of Ah/Al/Bh/Bl into stage via cp.async.
static __device__ __forceinline__ void load_chunk(
    char* stage, const bf16* __restrict__ Ah, const bf16* __restrict__ Al,
    const bf16* __restrict__ Bh, const bf16* __restrict__ Bl, int k0)
{
    const bf16* bases[4] = {Ah, Al, Bh, Bl};
    const int tid = threadIdx.x;
    uint32_t sbase = (uint32_t)__cvta_generic_to_shared(stage);
#pragma unroll
    for (int j = 0; j < 8; j++) {
        const int idx  = tid + j * 256;       // 0..2047
        const int tile = idx >> 9;
        const int w    = idx & 511;
        const int r    = w >> 2;
        const int c16  = w & 3;
        const bf16* g = bases[tile] + (size_t)r * Dk + k0 + c16 * 8;
        uint32_t s = sbase + tile * TILE_B + r * (ROWE * 2) + c16 * 16;
        cp_async16(s, g);
    }
}

struct WAcc { float v[4][4][4]; };   // [mf][nf][c0..c3]

// Full 3-split mainloop; acc must be zero-initialized by caller.
static __device__ __forceinline__ void mma_mainloop(
    const bf16* __restrict__ Ahi, const bf16* __restrict__ Alo,
    const bf16* __restrict__ Bhi, const bf16* __restrict__ Blo,
    int m0, int n0, char* smem, WAcc& acc)
{
    const int tid   = threadIdx.x;
    const int wid   = tid >> 5;
    const int lane  = tid & 31;
    const int warpM = wid >> 2;          // 0..1
    const int warpN = wid & 3;           // 0..3
    const int g     = lane >> 2;         // 0..7
    const int q     = lane & 3;          // 0..3

    const bf16* Ah = Ahi + (size_t)m0 * Dk;
    const bf16* Al = Alo + (size_t)m0 * Dk;
    const bf16* Bh = Bhi + (size_t)n0 * Dk;
    const bf16* Bl = Blo + (size_t)n0 * Dk;

    load_chunk(smem, Ah, Al, Bh, Bl, 0);
    cp_commit();

    for (int c = 0; c < NCH; c++) {
        if (c + 1 < NCH) {
            load_chunk(smem + ((c + 1) & 1) * STG_B, Ah, Al, Bh, Bl, (c + 1) * BKC);
            cp_commit();
            cp_wait<1>();
        } else {
            cp_wait<0>();
        }
        __syncthreads();

        const char* stg = smem + (c & 1) * STG_B;
        // byte offsets into a tile: row*80 + kh*32 + q*4 (+16 for hi-k regs)
#pragma unroll
        for (int kh = 0; kh < 2; kh++) {
            uint32_t bh[4][2], bl[4][2];
#pragma unroll
            for (int nf = 0; nf < 4; nf++) {
                const int n = warpN * 32 + nf * 8 + g;
                const int o = n * (ROWE * 2) + kh * 32 + q * 4;
                bh[nf][0] = *(const uint32_t*)(stg + 2 * TILE_B + o);
                bh[nf][1] = *(const uint32_t*)(stg + 2 * TILE_B + o + 16);
                bl[nf][0] = *(const uint32_t*)(stg + 3 * TILE_B + o);
                bl[nf][1] = *(const uint32_t*)(stg + 3 * TILE_B + o + 16);
            }
#pragma unroll
            for (int mf = 0; mf < 4; mf++) {
                const int r = warpM * 64 + mf * 16 + g;
                const int o = r * (ROWE * 2) + kh * 32 + q * 4;
                uint32_t ah[4], al[4];
                ah[0] = *(const uint32_t*)(stg + o);
                ah[1] = *(const uint32_t*)(stg + o + 8 * (ROWE * 2));
                ah[2] = *(const uint32_t*)(stg + o + 16);
                ah[3] = *(const uint32_t*)(stg + o + 8 * (ROWE * 2) + 16);
                al[0] = *(const uint32_t*)(stg + TILE_B + o);
                al[1] = *(const uint32_t*)(stg + TILE_B + o + 8 * (ROWE * 2));
                al[2] = *(const uint32_t*)(stg + TILE_B + o + 16);
                al[3] = *(const uint32_t*)(stg + TILE_B + o + 8 * (ROWE * 2) + 16);
#pragma unroll
                for (int nf = 0; nf < 4; nf++) {
                    MMA16816(acc.v[mf][nf], ah, bh[nf]);
                    MMA16816(acc.v[mf][nf], ah, bl[nf]);
                    MMA16816(acc.v[mf][nf], al, bh[nf]);
                }
            }
        }
        __syncthreads();
    }
}

// ---------------- QKV projection (scatter to [B,H,S,DF]) ----------------
__global__ __launch_bounds__(256, 1)
void qkv_mma_kernel(const float* __restrict__ bq, const float* __restrict__ bk,
                    const float* __restrict__ bv)
{
    extern __shared__ char smem[];
    const int z  = blockIdx.z;
    const int m0 = blockIdx.y * 128;
    const int n0 = blockIdx.x * 128;

    WAcc acc;
#pragma unroll
    for (int a = 0; a < 4; a++)
#pragma unroll
        for (int b = 0; b < 4; b++)
#pragma unroll
            for (int cc = 0; cc < 4; cc++) acc.v[a][b][cc] = 0.f;

    mma_mainloop(g_xhi[z], g_xlo[z], g_whi[z], g_wlo[z], m0, n0, smem, acc);

    const float* bias = (z == 0) ? bq : (z == 1) ? bk : bv;
    float* out        = (z == 0) ? g_Qp : (z == 1) ? g_Kp : g_Vp;

    const int lane  = threadIdx.x & 31;
    const int wid   = threadIdx.x >> 5;
    const int warpM = wid >> 2, warpN = wid & 3;
    const int g     = lane >> 2, q = lane & 3;

#pragma unroll
    for (int mf = 0; mf < 4; mf++) {
#pragma unroll
        for (int half = 0; half < 2; half++) {
            const int m  = m0 + warpM * 64 + mf * 16 + g + half * 8;
            const int bb = m / Sk;
            const int ss = m - bb * Sk;
            const size_t rowbase = ((size_t)bb * Hk) * Sk * DFk + (size_t)ss * DFk;
#pragma unroll
            for (int nf = 0; nf < 4; nf++) {
#pragma unroll
                for (int e = 0; e < 2; e++) {
                    const int n  = n0 + warpN * 32 + nf * 8 + q * 2 + e;
                    const int hh = n >> 6;
                    const int df = n & 63;
                    out[rowbase + (size_t)hh * Sk * DFk + df] =
                        acc.v[mf][nf][half * 2 + e] + bias[n];
                }
            }
        }
    }
}

// ---------------- output projection ----------------
__global__ __launch_bounds__(256, 1)
void out_mma_kernel(const float* __restrict__ bo, float* __restrict__ out)
{
    extern __shared__ char smem[];
    const int m0 = blockIdx.y * 128;
    const int n0 = blockIdx.x * 128;

    WAcc acc;
#pragma unroll
    for (int a = 0; a < 4; a++)
#pragma unroll
        for (int b = 0; b < 4; b++)
#pragma unroll
            for (int cc = 0; cc < 4; cc++) acc.v[a][b][cc] = 0.f;

    mma_mainloop(g_chi, g_clo, g_whi[3], g_wlo[3], m0, n0, smem, acc);

    const int lane  = threadIdx.x & 31;
    const int wid   = threadIdx.x >> 5;
    const int warpM = wid >> 2, warpN = wid & 3;
    const int g     = lane >> 2, q = lane & 3;

#pragma unroll
    for (int mf = 0; mf < 4; mf++) {
#pragma unroll
        for (int half = 0; half < 2; half++) {
            const int m = m0 + warpM * 64 + mf * 16 + g + half * 8;
#pragma unroll
            for (int nf = 0; nf < 4; nf++) {
                const int n = n0 + warpN * 32 + nf * 8 + q * 2;
                float2 v;
                v.x = acc.v[mf][nf][half * 2 + 0] + bo[n];
                v.y = acc.v[mf][nf][half * 2 + 1] + bo[n + 1];
                *(float2*)(out + (size_t)m * Dk + n) = v;
            }
        }
    }
}

// ---------------- fp32 -> bf16 hi/lo split ----------------
__global__ void cvt_kernel(const float* __restrict__ x, int which, int n4)
{
    const int i = blockIdx.x * blockDim.x + threadIdx.x;
    if (i >= n4) return;
    bf16* hi = (which < 3) ? g_xhi[which] : g_whi[which - 3];
    bf16* lo = (which < 3) ? g_xlo[which] : g_wlo[which - 3];
    float4 v = ((const float4*)x)[i];
    bf16 h0 = __float2bfloat16(v.x), h1 = __float2bfloat16(v.y);
    bf16 h2 = __float2bfloat16(v.z), h3 = __float2bfloat16(v.w);
    bf16 l0 = __float2bfloat16(v.x - __bfloat162float(h0));
    bf16 l1 = __float2bfloat16(v.y - __bfloat162float(h1));
    bf16 l2 = __float2bfloat16(v.z - __bfloat162float(h2));
    bf16 l3 = __float2bfloat16(v.w - __bfloat162float(h3));
    ((__nv_bfloat162*)hi)[2 * i]     = __halves2bfloat162(h0, h1);
    ((__nv_bfloat162*)hi)[2 * i + 1] = __halves2bfloat162(h2, h3);
    ((__nv_bfloat162*)lo)[2 * i]     = __halves2bfloat162(l0, l1);
    ((__nv_bfloat162*)lo)[2 * i + 1] = __halves2bfloat162(l2, l3);
}

// ---------------- attention (fp32; writes bf16 hi/lo ctx) ----------------
#define KV_LD 65
#define ATTN_SMEM_FLOATS (2 * Sk * KV_LD + 8 * Sk + 8 * DFk)

__global__ __launch_bounds__(256, 2)
void attn_kernel()
{
    extern __shared__ float sm[];
    float* Ks = sm;
    float* Vs = Ks + Sk * KV_LD;
    float* Ps = Vs + Sk * KV_LD;
    float* Qs = Ps + 8 * Sk;

    const int bh = blockIdx.x;
    const int bb = bh >> 3;
    const int hh = bh & 7;
    const size_t base = (size_t)bh * Sk * DFk;
    const float* Qg = g_Qp + base;
    const float* Kg = g_Kp + base;
    const float* Vg = g_Vp + base;

    const int tid = threadIdx.x;
    for (int i = tid; i < Sk * DFk; i += 256) {
        const int r = i >> 6;
        const int c = i & 63;
        Ks[r * KV_LD + c] = Kg[i];
        Vs[r * KV_LD + c] = Vg[i];
    }
    __syncthreads();

    const int w    = tid >> 5;
    const int lane = tid & 31;
    float* Pw = Ps + w * Sk;

    for (int qi = w; qi < Sk; qi += 8) {
        Qs[w * DFk + lane]      = Qg[qi * DFk + lane];
        Qs[w * DFk + 32 + lane] = Qg[qi * DFk + 32 + lane];
        __syncwarp();
        float qreg[DFk];
#pragma unroll
        for (int d = 0; d < DFk; d++) qreg[d] = Qs[w * DFk + d];

        const int nk = qi + 1;
        float sc[7];
        float mx = -INFINITY;
        int cnt = 0;
        for (int kk = lane; kk < nk; kk += 32) {
            const float* kr = Ks + kk * KV_LD;
            float s = 0.f;
#pragma unroll
            for (int d = 0; d < DFk; d++) s = fmaf(qreg[d], kr[d], s);
            s *= SCALE;
            sc[cnt++] = s;
            mx = fmaxf(mx, s);
        }
#pragma unroll
        for (int off = 16; off > 0; off >>= 1)
            mx = fmaxf(mx, __shfl_xor_sync(0xFFFFFFFFu, mx, off));

        float lsum = 0.f;
        cnt = 0;
        for (int kk = lane; kk < nk; kk += 32) {
            float e = expf(sc[cnt++] - mx);
            Pw[kk] = e;
            lsum += e;
        }
#pragma unroll
        for (int off = 16; off > 0; off >>= 1)
            lsum += __shfl_xor_sync(0xFFFFFFFFu, lsum, off);
        const float inv = 1.f / lsum;
        __syncwarp();

        float a0 = 0.f, a1 = 0.f;
        for (int kk = 0; kk < nk; kk++) {
            const float p = Pw[kk];
            a0 = fmaf(p, Vs[kk * KV_LD + lane],      a0);
            a1 = fmaf(p, Vs[kk * KV_LD + 32 + lane], a1);
        }
        a0 *= inv; a1 *= inv;
        if (qi == 0) { a0 = 0.f; a1 = 0.f; }

        const size_t o = ((size_t)bb * Sk + qi) * Dk + hh * DFk;
        bf16 h0 = __float2bfloat16(a0);
        bf16 h1 = __float2bfloat16(a1);
        g_chi[o + lane]      = h0;
        g_chi[o + lane + 32] = h1;
        g_clo[o + lane]      = __float2bfloat16(a0 - __bfloat162float(h0));
        g_clo[o + lane + 32] = __float2bfloat16(a1 - __bfloat162float(h1));
        __syncwarp();
    }
}

// ---------------- launch ----------------
extern "C" void kernel_launch(void* const* d_in, const int* in_sizes, int n_in,
                              void* d_out, int out_size)
{
    const float* q  = (const float*)d_in[0];
    const float* k  = (const float*)d_in[1];
    const float* v  = (const float*)d_in[2];
    const float* Wq = (const float*)d_in[3];
    const float* bq = (const float*)d_in[4];
    const float* Wk = (const float*)d_in[5];
    const float* bk = (const float*)d_in[6];
    const float* Wv = (const float*)d_in[7];
    const float* bv = (const float*)d_in[8];
    const float* Wo = (const float*)d_in[9];
    const float* bo = (const float*)d_in[10];
    float* out = (float*)d_out;

    const int nx4 = ROWS * Dk / 4;
    const int nw4 = Dk * Dk / 4;
    cvt_kernel<<<nx4 / 256, 256>>>(q,  0, nx4);
    cvt_kernel<<<nx4 / 256, 256>>>(k,  1, nx4);
    cvt_kernel<<<nx4 / 256, 256>>>(v,  2, nx4);
    cvt_kernel<<<nw4 / 256, 256>>>(Wq, 3, nw4);
    cvt_kernel<<<nw4 / 256, 256>>>(Wk, 4, nw4);
    cvt_kernel<<<nw4 / 256, 256>>>(Wv, 5, nw4);
    cvt_kernel<<<nw4 / 256, 256>>>(Wo, 6, nw4);

    cudaFuncSetAttribute(qkv_mma_kernel, cudaFuncAttributeMaxDynamicSharedMemorySize,
                         GEMM_SMEM);
    qkv_mma_kernel<<<dim3(Dk / 128, ROWS / 128, 3), 256, GEMM_SMEM>>>(bq, bk, bv);

    const int attn_smem = ATTN_SMEM_FLOATS * (int)sizeof(float);
    cudaFuncSetAttribute(attn_kernel, cudaFuncAttributeMaxDynamicSharedMemorySize,
                         attn_smem);
    attn_kernel<<<Bk * Hk, 256, attn_smem>>>();

    cudaFuncSetAttribute(out_mma_kernel, cudaFuncAttributeMaxDynamicSharedMemorySize,
                         GEMM_SMEM);
    out_mma_kernel<<<dim3(Dk / 128, ROWS / 128, 1), 256, GEMM_SMEM>>>(bo, out);
}